// round 14
// baseline (speedup 1.0000x reference)
#include <cuda_runtime.h>
#include <cuda_fp16.h>
#include <cstdint>

#define N_MSG 16384
#define NNB 10
#define IN_F 135
#define KQ 160            // padded fmess K (multiple of 32)
#define H 256
#define HEADS 4
#define DEPTH 5
#define NEG_INF -1e18f

// ---------------- fp32 state ------------------------------------------------
__device__ float g_h[N_MSG * H];
__device__ float g_V[N_MSG * H];         // V only; K never materialized
__device__ float g_sumh[N_MSG * H];
__device__ float g_z[N_MSG * H];
__device__ float g_F[N_MSG * 3 * H];
__device__ float g_qs[N_MSG * HEADS];
__device__ float g_ks[N_MSG * HEADS];
__device__ float g_tzr[2 * H];           // step-0: bv @ [Wz2|Ur]^T
// ---------------- fp16 GEMM operands (single-pass) ---------------------------
__device__ __align__(16) __half g_h16[N_MSG * H];
__device__ __align__(16) __half g_sh16[N_MSG * H];
__device__ __align__(16) __half g_rs16[N_MSG * H];
__device__ __align__(16) __half g_f16[N_MSG * KQ];
__device__ __align__(16) __half g_Wkv16[512 * H];
__device__ __align__(16) __half g_Wzr16[512 * H];
__device__ __align__(16) __half g_Wh216[H * H];
__device__ __align__(16) __half g_Wpre16[1024 * KQ];
__device__ float g_bkv[512];
__device__ float g_bpre[1024];

// ---------------- helpers ----------------------------------------------------
__device__ __forceinline__ float sigmoidf_(float x) { return 1.0f / (1.0f + expf(-x)); }
__device__ __forceinline__ float lrelu_(float x) { return x >= 0.f ? x : 0.01f * x; }

__device__ __forceinline__ uint32_t smem_u32(const void* p) {
    uint32_t a;
    asm("{ .reg .u64 t; cvta.to.shared.u64 t, %1; cvt.u32.u64 %0, t; }" : "=r"(a) : "l"(p));
    return a;
}
__device__ __forceinline__ void ldsm_x4(uint32_t& r0, uint32_t& r1, uint32_t& r2,
                                        uint32_t& r3, uint32_t addr) {
    asm volatile("ldmatrix.sync.aligned.m8n8.x4.shared.b16 {%0,%1,%2,%3}, [%4];"
                 : "=r"(r0), "=r"(r1), "=r"(r2), "=r"(r3) : "r"(addr));
}
__device__ __forceinline__ void mma16816(float* d, const uint32_t* a, const uint32_t* b) {
    asm volatile(
        "mma.sync.aligned.m16n8k16.row.col.f32.f16.f16.f32 "
        "{%0,%1,%2,%3}, {%4,%5,%6,%7}, {%8,%9}, {%0,%1,%2,%3};"
        : "+f"(d[0]), "+f"(d[1]), "+f"(d[2]), "+f"(d[3])
        : "r"(a[0]), "r"(a[1]), "r"(a[2]), "r"(a[3]), "r"(b[0]), "r"(b[1]));
}
#define CP16(dst, src) \
    asm volatile("cp.async.cg.shared.global [%0], [%1], 16;" :: "r"(dst), "l"(src))
#define CP_COMMIT() asm volatile("cp.async.commit_group;" ::: "memory")
#define CP_WAIT(n)  asm volatile("cp.async.wait_group %0;" :: "n"(n) : "memory")

// ---------------- pad fmess ---------------------------------------------------
__global__ void pad_fmess(const float* __restrict__ fmess) {
    int i = blockIdx.x * blockDim.x + threadIdx.x;
    if (i >= N_MSG * KQ) return;
    int n = i / KQ, c = i % KQ;
    float x = (c < IN_F) ? fmess[n * IN_F + c] : 0.0f;
    g_f16[i] = __float2half_rn(x);
}

// ---------------- weight packing --------------------------------------------
__global__ void pack_all(const float* __restrict__ Wq, const float* __restrict__ bq,
                         const float* __restrict__ Wk, const float* __restrict__ bk,
                         const float* __restrict__ Wv, const float* __restrict__ bv,
                         const float* __restrict__ Wz, const float* __restrict__ bz,
                         const float* __restrict__ Wr, const float* __restrict__ Ur,
                         const float* __restrict__ bur,
                         const float* __restrict__ Wh, const float* __restrict__ bh) {
    int i = blockIdx.x * blockDim.x + threadIdx.x;
    const int WIDE = IN_F + H;  // 391
    if (i < 512 * H) {
        int n = i / H, k = i % H;
        float kv = (n < H) ? Wk[n * H + k] : Wv[(n - H) * H + k];
        g_Wkv16[i] = __float2half_rn(kv);
        float zr = (n < H) ? Wz[n * WIDE + IN_F + k] : Ur[(n - H) * H + k];
        g_Wzr16[i] = __float2half_rn(zr);
    }
    if (i < H * H) {
        int n = i / H, k = i % H;
        g_Wh216[i] = __float2half_rn(Wh[n * WIDE + IN_F + k]);
    }
    if (i < 1024 * KQ) {
        int n = i / KQ, k = i % KQ;
        float v = 0.0f;
        if (k < IN_F) {
            if (n < 256) v = Wz[n * WIDE + k];
            else if (n < 512) v = Wr[(n - 256) * IN_F + k];
            else if (n < 768) v = Wh[(n - 512) * WIDE + k];
            else v = Wq[(n - 768) * IN_F + k];
        }
        g_Wpre16[i] = __float2half_rn(v);
    }
    if (i < 512) g_bkv[i] = (i < 256) ? bk[i] : bv[i - 256];
    if (i < 1024) {
        float b = (i < 256) ? bz[i] : (i < 512) ? bur[i - 256]
                : (i < 768) ? bh[i - 512] : bq[i - 768];
        g_bpre[i] = b;
    }
}

// ---------------- step-0 rank-1 kernels --------------------------------------
__global__ void bv_t_kernel(const float* __restrict__ Wz, const float* __restrict__ Ur,
                            const float* __restrict__ bv) {
    const int WIDE = IN_F + H;
    int o = blockIdx.x * 8 + (threadIdx.x >> 5);
    int lane = threadIdx.x & 31;
    float s = 0.f;
#pragma unroll
    for (int t = 0; t < 8; t++) {
        int k = lane + 32 * t;
        float w = (o < 256) ? Wz[o * WIDE + IN_F + k] : Ur[(o - 256) * H + k];
        s += bv[k] * w;
    }
    for (int d = 16; d; d >>= 1) s += __shfl_xor_sync(0xffffffffu, s, d);
    if (lane == 0) g_tzr[o] = s;
}

__global__ void zr0_kernel(const float* __restrict__ bv) {
    int i = blockIdx.x * blockDim.x + threadIdx.x;   // over N*H
    int n = i >> 8, c = i & 255;
    float b = bv[c];
    g_sumh[i] = b;
    g_z[i] = sigmoidf_(g_F[(size_t)n * 768 + c] + g_tzr[c]);
    float rv = sigmoidf_(g_F[(size_t)n * 768 + 256 + c] + g_tzr[256 + c]) * b;
    g_rs16[i] = __float2half_rn(rv);
}

// ---------------- mma.sync GEMM: 64x128 CTA tile, 32x32 warp tiles -----------
// 8 warps (2 M-groups x 4 N-groups), 3 CTAs/SM for 24 warps/SM occupancy.
#define GT_PRE 0
#define GT_KV 1
#define GT_ZR 2
#define GT_FINAL 3
#define STR 40
#define ASTG (64 * STR * 2)    // 5120 B per A stage
#define BSTG (128 * STR * 2)   // 10240 B per B stage
#define SMEM_DYN (4 * (ASTG + BSTG))   // 61440 B

__global__ __launch_bounds__(256, 3)
void gemm_mma(const __half* __restrict__ Aw, const __half* __restrict__ Bw,
              const float* __restrict__ bias, const float* __restrict__ alpha,
              int Kp, int mode, float* __restrict__ dst) {
    extern __shared__ __half dsm[];
    const uint32_t sA0 = smem_u32(dsm);
    const uint32_t sB0 = sA0 + 4 * ASTG;

    const int tid = threadIdx.x, lane = tid & 31, wid = tid >> 5;
    const int wm = (wid & 1) * 32, wn = (wid >> 1) * 32;
    const int bx = blockIdx.x;
    const int row0 = blockIdx.y * 64, col0 = bx * 128;

    const int arow = wm + (lane & 15), ak = (lane >> 4) << 3;
    const int g = lane >> 3;
    const int brow = wn + ((g >> 1) << 3) + (lane & 7), bk = (g & 1) << 3;
    const uint32_t aoff_l = (uint32_t)(arow * STR + ak) * 2;
    const uint32_t boff_l = (uint32_t)(brow * STR + bk) * 2;

    const int NC = Kp >> 5;

    auto issue = [&](int c) {
        int kk = c << 5;
        const uint32_t abase = sA0 + (uint32_t)(c & 3) * ASTG;
        const uint32_t bbase = sB0 + (uint32_t)(c & 3) * BSTG;
        {   // A: 64 rows x 32 cols = 256 x 16B, one per thread
            int row = tid >> 2, coli = (tid & 3) << 3;
            CP16(abase + (uint32_t)(row * STR + coli) * 2,
                 Aw + (size_t)(row0 + row) * Kp + kk + coli);
        }
#pragma unroll
        for (int i = 0; i < 2; i++) {   // B: 128 rows x 32 cols = 512 x 16B
            int t2 = tid + (i << 8);
            int row = t2 >> 2, coli = (t2 & 3) << 3;
            CP16(bbase + (uint32_t)(row * STR + coli) * 2,
                 Bw + (size_t)(col0 + row) * Kp + kk + coli);
        }
        CP_COMMIT();
    };

    float acc[2][4][4];
#pragma unroll
    for (int i = 0; i < 2; i++)
#pragma unroll
        for (int j = 0; j < 4; j++)
#pragma unroll
            for (int q = 0; q < 4; q++) acc[i][j][q] = 0.f;

    issue(0); issue(1); issue(2);

    for (int c = 0; c < NC; c++) {
        const int allowed = NC - 1 - c;
        if (allowed >= 2)      CP_WAIT(2);
        else if (allowed == 1) CP_WAIT(1);
        else                   CP_WAIT(0);
        __syncthreads();
        if (c + 3 < NC) issue(c + 3);

        const uint32_t abase = sA0 + (uint32_t)(c & 3) * ASTG + aoff_l;
        const uint32_t bbase = sB0 + (uint32_t)(c & 3) * BSTG + boff_l;
#pragma unroll
        for (int kk2 = 0; kk2 < 2; kk2++) {
            uint32_t a[2][4], bf[4][2];
#pragma unroll
            for (int mt = 0; mt < 2; mt++)
                ldsm_x4(a[mt][0], a[mt][1], a[mt][2], a[mt][3],
                        abase + mt * 16 * STR * 2 + kk2 * 32);
#pragma unroll
            for (int np = 0; np < 2; np++)
                ldsm_x4(bf[2 * np][0], bf[2 * np][1], bf[2 * np + 1][0], bf[2 * np + 1][1],
                        bbase + np * 16 * STR * 2 + kk2 * 32);
#pragma unroll
            for (int mt = 0; mt < 2; mt++)
#pragma unroll
                for (int nt = 0; nt < 4; nt++)
                    mma16816(acc[mt][nt], a[mt], bf[nt]);
        }
    }

    // ---------------- fused epilogue (atomic-free; scores only) ----------------
    __syncthreads();   // stage smem is dead; reuse as reduction scratch
    float* scr = reinterpret_cast<float*>(dsm);
    const bool ks_blk = (mode == GT_KV && bx < 2);
    const bool qs_blk = (mode == GT_PRE && bx >= 6);
    const bool score_blk = ks_blk || qs_blk;
    const int hl = wn >> 6;            // head-local (0/1)
    const int ppair = (wn >> 5) & 1;   // partial slot within 64-col head half

    auto apply = [&](int r, int c, float v0, float v1) -> float {
        if (mode == GT_PRE) {
            if (c < 768) {
                g_F[(size_t)r * 768 + c] = v0 + bias[c];
                g_F[(size_t)r * 768 + c + 1] = v1 + bias[c + 1];
                return 0.f;
            }
            int head = (bx - 6) * 2 + hl;
            return lrelu_(v0 + bias[c]) * alpha[head * 128 + (c & 63)]
                 + lrelu_(v1 + bias[c + 1]) * alpha[head * 128 + (c & 63) + 1];
        } else if (mode == GT_KV) {
            if (c < 256) {
                int head = bx * 2 + hl;
                return lrelu_(v0 + bias[c]) * alpha[head * 128 + 64 + (c & 63)]
                     + lrelu_(v1 + bias[c + 1]) * alpha[head * 128 + 64 + (c & 63) + 1];
            }
            dst[(size_t)r * 256 + c - 256] = v0 + bias[c];
            dst[(size_t)r * 256 + c - 255] = v1 + bias[c + 1];
            return 0.f;
        } else if (mode == GT_ZR) {
            if (c < 256) {
                g_z[(size_t)r * 256 + c] = sigmoidf_(g_F[(size_t)r * 768 + c] + v0);
                g_z[(size_t)r * 256 + c + 1] = sigmoidf_(g_F[(size_t)r * 768 + c + 1] + v1);
            } else {
                int cc = c - 256;
                float rv0 = sigmoidf_(g_F[(size_t)r * 768 + 256 + cc] + v0) *
                            g_sumh[(size_t)r * 256 + cc];
                float rv1 = sigmoidf_(g_F[(size_t)r * 768 + 257 + cc] + v1) *
                            g_sumh[(size_t)r * 256 + cc + 1];
                g_rs16[(size_t)r * 256 + cc] = __float2half_rn(rv0);
                g_rs16[(size_t)r * 256 + cc + 1] = __float2half_rn(rv1);
            }
            return 0.f;
        } else {  // GT_FINAL
            float pre0 = tanhf(g_F[(size_t)r * 768 + 512 + c] + v0);
            float pre1 = tanhf(g_F[(size_t)r * 768 + 513 + c] + v1);
            float z0 = g_z[(size_t)r * 256 + c], z1 = g_z[(size_t)r * 256 + c + 1];
            float s0 = g_sumh[(size_t)r * 256 + c], s1 = g_sumh[(size_t)r * 256 + c + 1];
            float nh0 = (1.0f - z0) * s0 + z0 * pre0;
            float nh1 = (1.0f - z1) * s1 + z1 * pre1;
            if (r == 0) { nh0 = 0.0f; nh1 = 0.0f; }
            dst[(size_t)r * 256 + c] = nh0;
            dst[(size_t)r * 256 + c + 1] = nh1;
            g_h16[(size_t)r * 256 + c] = __float2half_rn(nh0);
            g_h16[(size_t)r * 256 + c + 1] = __float2half_rn(nh1);
            return 0.f;
        }
    };

    float red[2][2];
#pragma unroll
    for (int mt = 0; mt < 2; mt++) { red[mt][0] = 0.f; red[mt][1] = 0.f; }

#pragma unroll
    for (int mt = 0; mt < 2; mt++) {
#pragma unroll
        for (int nt = 0; nt < 4; nt++) {
            int r = row0 + wm + mt * 16 + (lane >> 2);
            int c = col0 + wn + nt * 8 + ((lane & 3) << 1);
            red[mt][0] += apply(r, c, acc[mt][nt][0], acc[mt][nt][1]);
            red[mt][1] += apply(r + 8, c, acc[mt][nt][2], acc[mt][nt][3]);
        }
    }

    if (score_blk) {
#pragma unroll
        for (int mt = 0; mt < 2; mt++) {
#pragma unroll
            for (int j = 0; j < 2; j++) {
                red[mt][j] += __shfl_xor_sync(0xffffffffu, red[mt][j], 1);
                red[mt][j] += __shfl_xor_sync(0xffffffffu, red[mt][j], 2);
            }
        }
        if ((lane & 3) == 0) {
            int rl = wm + (lane >> 2);
#pragma unroll
            for (int mt = 0; mt < 2; mt++) {
                int row = rl + mt * 16;
                scr[(row * 2 + hl) * 2 + ppair] = red[mt][0];
                scr[((row + 8) * 2 + hl) * 2 + ppair] = red[mt][1];
            }
        }
        __syncthreads();
        if (tid < 128) {
            int row = tid >> 1, h2 = tid & 1;
            float val = scr[(row * 2 + h2) * 2] + scr[(row * 2 + h2) * 2 + 1];
            if (ks_blk) g_ks[(row0 + row) * 4 + bx * 2 + h2] = val;
            else        g_qs[(row0 + row) * 4 + (bx - 6) * 2 + h2] = val;
        }
    }
}

// ---------------- attention ---------------------------------------------------
// Mask: neighbor j is padding iff j == 0 (row 0 forced to zero every step;
// steps >= 1 rows are generically nonzero; step 0 handled by rank-1 shortcut).
__global__ __launch_bounds__(256)
void attn_kernel(const int* __restrict__ bgraph, const float* __restrict__ abias) {
    int n = blockIdx.x;
    int t = threadIdx.x;
    __shared__ int js[NNB];
    __shared__ float sc[NNB][HEADS];
    __shared__ float wgt[NNB][HEADS];
    if (t < NNB) js[t] = bgraph[n * NNB + t];
    __syncthreads();
    if (t < NNB * HEADS) {
        int m = t >> 2, hh = t & 3;
        int j = js[m];
        float s = g_qs[n * 4 + hh] + g_ks[j * 4 + hh] + abias[hh];
        if (j == 0) s = NEG_INF;
        sc[m][hh] = s;
    }
    __syncthreads();
    if (t < HEADS) {
        float mx = -INFINITY;
#pragma unroll
        for (int m = 0; m < NNB; m++) mx = fmaxf(mx, sc[m][t]);
        float e[NNB], ssum = 0.f;
#pragma unroll
        for (int m = 0; m < NNB; m++) { e[m] = expf(sc[m][t] - mx); ssum += e[m]; }
        float inv = 1.0f / ssum;
#pragma unroll
        for (int m = 0; m < NNB; m++) wgt[m][t] = e[m] * inv;
    }
    __syncthreads();
    int hh = t >> 6;
    float acc = 0.f;
#pragma unroll
    for (int m = 0; m < NNB; m++)
        acc += wgt[m][hh] * g_V[(size_t)js[m] * 256 + t];
    size_t idx = (size_t)n * H + t;
    g_sumh[idx] = acc;
    g_sh16[idx] = __float2half_rn(acc);
}

// ---------------- launch -------------------------------------------------------
static void* symaddr(const void* s) {
    void* p = nullptr;
    cudaGetSymbolAddress(&p, s);
    return p;
}

extern "C" void kernel_launch(void* const* d_in, const int* in_sizes, int n_in,
                              void* d_out, int out_size) {
    const float* fmess = (const float*)d_in[0];
    const int*   bgraph = (const int*)d_in[1];
    const float* Wq = (const float*)d_in[2];
    const float* bq = (const float*)d_in[3];
    const float* Wk = (const float*)d_in[4];
    const float* bk = (const float*)d_in[5];
    const float* Wv = (const float*)d_in[6];
    const float* bv = (const float*)d_in[7];
    const float* alpha = (const float*)d_in[8];
    const float* abias = (const float*)d_in[9];
    const float* Wz = (const float*)d_in[10];
    const float* bz = (const float*)d_in[11];
    const float* Wr = (const float*)d_in[12];
    const float* Ur = (const float*)d_in[13];
    const float* bur = (const float*)d_in[14];
    const float* Wh = (const float*)d_in[15];
    const float* bh = (const float*)d_in[16];
    float* out = (float*)d_out;

    float* p_h = (float*)symaddr(g_h);
    float* p_V = (float*)symaddr(g_V);
    const __half* a_h16  = (const __half*)symaddr(g_h16);
    const __half* a_sh16 = (const __half*)symaddr(g_sh16);
    const __half* a_rs16 = (const __half*)symaddr(g_rs16);
    const __half* a_f16  = (const __half*)symaddr(g_f16);
    const __half* w_kv   = (const __half*)symaddr(g_Wkv16);
    const __half* w_zr   = (const __half*)symaddr(g_Wzr16);
    const __half* w_h2   = (const __half*)symaddr(g_Wh216);
    const __half* w_pr   = (const __half*)symaddr(g_Wpre16);
    const float* b_kv  = (const float*)symaddr(g_bkv);
    const float* b_pre = (const float*)symaddr(g_bpre);

    cudaFuncSetAttribute(gemm_mma, cudaFuncAttributeMaxDynamicSharedMemorySize, SMEM_DYN);

    pad_fmess<<<(N_MSG * KQ + 255) / 256, 256>>>(fmess);
    pack_all<<<(1024 * KQ + 255) / 256, 256>>>(Wq, bq, Wk, bk, Wv, bv, Wz, bz,
                                               Wr, Ur, bur, Wh, bh);
    bv_t_kernel<<<64, 256>>>(Wz, Ur, bv);

    // PRE: [F(768) | qscore] = fmess @ Wpre^T + bpre (qscore fused, blocks x>=6)
    gemm_mma<<<dim3(8, 256), 256, SMEM_DYN>>>(a_f16, w_pr, b_pre, alpha,
                                              KQ, GT_PRE, nullptr);

    // ---- step 0 (exact rank-1 shortcut: h=0 => sum_h = bv for every row) ----
    zr0_kernel<<<N_MSG * H / 256, 256>>>(bv);
    gemm_mma<<<dim3(2, 256), 256, SMEM_DYN>>>(a_rs16, w_h2, nullptr, nullptr,
                                              H, GT_FINAL, p_h);

    // ---- steps 1..DEPTH-1 ----
    for (int step = 1; step < DEPTH; step++) {
        // KV: blocks x<2 reduce kscore (K not stored); x>=2 store V
        gemm_mma<<<dim3(4, 256), 256, SMEM_DYN>>>(a_h16, w_kv, b_kv, alpha,
                                                  H, GT_KV, p_V);
        attn_kernel<<<N_MSG, 256>>>(bgraph, abias);
        gemm_mma<<<dim3(4, 256), 256, SMEM_DYN>>>(a_sh16, w_zr, nullptr, nullptr,
                                                  H, GT_ZR, nullptr);
        gemm_mma<<<dim3(2, 256), 256, SMEM_DYN>>>(a_rs16, w_h2, nullptr, nullptr,
                                                  H, GT_FINAL,
                                                  step == DEPTH - 1 ? out : p_h);
    }
    (void)in_sizes; (void)n_in; (void)out_size;
}

// round 15
// speedup vs baseline: 1.5181x; 1.5181x over previous
#include <cuda_runtime.h>
#include <cuda_fp16.h>
#include <cstdint>

#define N_MSG 16384
#define NNB 10
#define IN_F 135
#define KQ 160            // padded fmess K (multiple of 32)
#define H 256
#define HEADS 4
#define DEPTH 5
#define NEG_INF -1e18f

// ---------------- fp32 state ------------------------------------------------
__device__ float g_h[N_MSG * H];
__device__ float g_V[N_MSG * H];         // V only; K never materialized
__device__ float g_sumh[N_MSG * H];
__device__ float g_z[N_MSG * H];
__device__ float g_F[N_MSG * 3 * H];
__device__ float g_qs[N_MSG * HEADS];
__device__ float g_ks[N_MSG * HEADS];
__device__ float g_tzr[2 * H];           // step-0: bv @ [Wz2|Ur]^T
// ---------------- fp16 GEMM operands (single-pass) ---------------------------
__device__ __align__(16) __half g_h16[N_MSG * H];
__device__ __align__(16) __half g_sh16[N_MSG * H];
__device__ __align__(16) __half g_rs16[N_MSG * H];
__device__ __align__(16) __half g_f16[N_MSG * KQ];
__device__ __align__(16) __half g_Wkv16[512 * H];
__device__ __align__(16) __half g_Wzr16[512 * H];
__device__ __align__(16) __half g_Wh216[H * H];
__device__ __align__(16) __half g_Wpre16[1024 * KQ];
__device__ float g_bkv[512];
__device__ float g_bpre[1024];

// ---------------- helpers ----------------------------------------------------
__device__ __forceinline__ float sigmoidf_(float x) { return 1.0f / (1.0f + expf(-x)); }
__device__ __forceinline__ float lrelu_(float x) { return x >= 0.f ? x : 0.01f * x; }

__device__ __forceinline__ uint32_t smem_u32(const void* p) {
    uint32_t a;
    asm("{ .reg .u64 t; cvta.to.shared.u64 t, %1; cvt.u32.u64 %0, t; }" : "=r"(a) : "l"(p));
    return a;
}
__device__ __forceinline__ void ldsm_x4(uint32_t& r0, uint32_t& r1, uint32_t& r2,
                                        uint32_t& r3, uint32_t addr) {
    asm volatile("ldmatrix.sync.aligned.m8n8.x4.shared.b16 {%0,%1,%2,%3}, [%4];"
                 : "=r"(r0), "=r"(r1), "=r"(r2), "=r"(r3) : "r"(addr));
}
__device__ __forceinline__ void mma16816(float* d, const uint32_t* a, const uint32_t* b) {
    asm volatile(
        "mma.sync.aligned.m16n8k16.row.col.f32.f16.f16.f32 "
        "{%0,%1,%2,%3}, {%4,%5,%6,%7}, {%8,%9}, {%0,%1,%2,%3};"
        : "+f"(d[0]), "+f"(d[1]), "+f"(d[2]), "+f"(d[3])
        : "r"(a[0]), "r"(a[1]), "r"(a[2]), "r"(a[3]), "r"(b[0]), "r"(b[1]));
}
#define CP16(dst, src) \
    asm volatile("cp.async.cg.shared.global [%0], [%1], 16;" :: "r"(dst), "l"(src))
#define CP_COMMIT() asm volatile("cp.async.commit_group;" ::: "memory")
#define CP_WAIT(n)  asm volatile("cp.async.wait_group %0;" :: "n"(n) : "memory")

// ---------------- merged setup: pad fmess + pack weights + bv_t --------------
#define PAD_BLOCKS ((N_MSG * KQ) / 256)   // 10240
__global__ void setup_all(const float* __restrict__ fmess,
                          const float* __restrict__ Wq, const float* __restrict__ bq,
                          const float* __restrict__ Wk, const float* __restrict__ bk,
                          const float* __restrict__ Wv, const float* __restrict__ bv,
                          const float* __restrict__ Wz, const float* __restrict__ bz,
                          const float* __restrict__ Wr, const float* __restrict__ Ur,
                          const float* __restrict__ bur,
                          const float* __restrict__ Wh, const float* __restrict__ bh) {
    const int WIDE = IN_F + H;  // 391
    int b = blockIdx.x;
    if (b >= PAD_BLOCKS) {
        // bv_t: t = bv @ [Wz2 | Ur]^T (64 blocks x 8 warps = 512 outputs)
        int o = (b - PAD_BLOCKS) * 8 + (threadIdx.x >> 5);
        int lane = threadIdx.x & 31;
        float s = 0.f;
#pragma unroll
        for (int t = 0; t < 8; t++) {
            int k = lane + 32 * t;
            float w = (o < 256) ? Wz[o * WIDE + IN_F + k] : Ur[(o - 256) * H + k];
            s += bv[k] * w;
        }
        for (int d = 16; d; d >>= 1) s += __shfl_xor_sync(0xffffffffu, s, d);
        if (lane == 0) g_tzr[o] = s;
        return;
    }
    int i = b * 256 + threadIdx.x;
    {   // pad/convert fmess
        int n = i / KQ, c = i % KQ;
        float x = (c < IN_F) ? fmess[n * IN_F + c] : 0.0f;
        g_f16[i] = __float2half_rn(x);
    }
    if (i < 512 * H) {
        int n = i / H, k = i % H;
        float kv = (n < H) ? Wk[n * H + k] : Wv[(n - H) * H + k];
        g_Wkv16[i] = __float2half_rn(kv);
        float zr = (n < H) ? Wz[n * WIDE + IN_F + k] : Ur[(n - H) * H + k];
        g_Wzr16[i] = __float2half_rn(zr);
    }
    if (i < H * H) {
        int n = i / H, k = i % H;
        g_Wh216[i] = __float2half_rn(Wh[n * WIDE + IN_F + k]);
    }
    if (i < 1024 * KQ) {
        int n = i / KQ, k = i % KQ;
        float v = 0.0f;
        if (k < IN_F) {
            if (n < 256) v = Wz[n * WIDE + k];
            else if (n < 512) v = Wr[(n - 256) * IN_F + k];
            else if (n < 768) v = Wh[(n - 512) * WIDE + k];
            else v = Wq[(n - 768) * IN_F + k];
        }
        g_Wpre16[i] = __float2half_rn(v);
    }
    if (i < 512) g_bkv[i] = (i < 256) ? bk[i] : bv[i - 256];
    if (i < 1024) {
        float bb = (i < 256) ? bz[i] : (i < 512) ? bur[i - 256]
                 : (i < 768) ? bh[i - 512] : bq[i - 768];
        g_bpre[i] = bb;
    }
}

// ---------------- step-0 elementwise -----------------------------------------
__global__ void zr0_kernel(const float* __restrict__ bv) {
    int i = blockIdx.x * blockDim.x + threadIdx.x;   // over N*H
    int n = i >> 8, c = i & 255;
    float b = bv[c];
    g_sumh[i] = b;
    g_z[i] = sigmoidf_(g_F[(size_t)n * 768 + c] + g_tzr[c]);
    float rv = sigmoidf_(g_F[(size_t)n * 768 + 256 + c] + g_tzr[256 + c]) * b;
    g_rs16[i] = __float2half_rn(rv);
}

// ---------------- mma.sync GEMM: 128x128 tile (R13 config, best known) -------
#define GT_PRE 0
#define GT_KV 1
#define GT_ZR 2
#define GT_FINAL 3
#define STR 40
#define STAGEB (128 * STR * 2)
#define SMEM_DYN (8 * STAGEB)

__global__ __launch_bounds__(256, 2)
void gemm_mma(const __half* __restrict__ Aw, const __half* __restrict__ Bw,
              const float* __restrict__ bias, const float* __restrict__ alpha,
              int Kp, int mode, float* __restrict__ dst) {
    extern __shared__ __half dsm[];
    const uint32_t sA0 = smem_u32(dsm);
    const uint32_t sB0 = sA0 + 4 * STAGEB;

    const int tid = threadIdx.x, lane = tid & 31, wid = tid >> 5;
    const int wm = (wid & 1) * 64, wn = (wid >> 1) * 32;
    const int bx = blockIdx.x;
    const int row0 = blockIdx.y * 128, col0 = bx * 128;

    const int arow = wm + (lane & 15), ak = (lane >> 4) << 3;
    const int g = lane >> 3;
    const int brow = wn + ((g >> 1) << 3) + (lane & 7), bk = (g & 1) << 3;
    const uint32_t aoff_l = (uint32_t)(arow * STR + ak) * 2;
    const uint32_t boff_l = (uint32_t)(brow * STR + bk) * 2;

    const int NC = Kp >> 5;

    auto issue = [&](int c) {
        int kk = c << 5;
        const uint32_t abase = sA0 + (uint32_t)(c & 3) * STAGEB;
        const uint32_t bbase = sB0 + (uint32_t)(c & 3) * STAGEB;
#pragma unroll
        for (int i = 0; i < 2; i++) {
            int t2 = tid + (i << 8);
            int row = t2 >> 2, coli = (t2 & 3) << 3;
            uint32_t so = (uint32_t)(row * STR + coli) * 2;
            CP16(abase + so, Aw + (size_t)(row0 + row) * Kp + kk + coli);
            CP16(bbase + so, Bw + (size_t)(col0 + row) * Kp + kk + coli);
        }
        CP_COMMIT();
    };

    float acc[4][4][4];
#pragma unroll
    for (int i = 0; i < 4; i++)
#pragma unroll
        for (int j = 0; j < 4; j++)
#pragma unroll
            for (int q = 0; q < 4; q++) acc[i][j][q] = 0.f;

    issue(0); issue(1); issue(2);

    for (int c = 0; c < NC; c++) {
        const int allowed = NC - 1 - c;
        if (allowed >= 2)      CP_WAIT(2);
        else if (allowed == 1) CP_WAIT(1);
        else                   CP_WAIT(0);
        __syncthreads();
        if (c + 3 < NC) issue(c + 3);

        const uint32_t abase = sA0 + (uint32_t)(c & 3) * STAGEB + aoff_l;
        const uint32_t bbase = sB0 + (uint32_t)(c & 3) * STAGEB + boff_l;
#pragma unroll
        for (int kk2 = 0; kk2 < 2; kk2++) {
            uint32_t a[4][4], bf[4][2];
#pragma unroll
            for (int mt = 0; mt < 4; mt++)
                ldsm_x4(a[mt][0], a[mt][1], a[mt][2], a[mt][3],
                        abase + mt * 16 * STR * 2 + kk2 * 32);
#pragma unroll
            for (int np = 0; np < 2; np++)
                ldsm_x4(bf[2 * np][0], bf[2 * np][1], bf[2 * np + 1][0], bf[2 * np + 1][1],
                        bbase + np * 16 * STR * 2 + kk2 * 32);
#pragma unroll
            for (int mt = 0; mt < 4; mt++)
#pragma unroll
                for (int nt = 0; nt < 4; nt++)
                    mma16816(acc[mt][nt], a[mt], bf[nt]);
        }
    }

    // ---------------- fused epilogue (atomic-free; scores only) ----------------
    __syncthreads();
    float* scr = reinterpret_cast<float*>(dsm);
    const bool ks_blk = (mode == GT_KV && bx < 2);
    const bool qs_blk = (mode == GT_PRE && bx >= 6);
    const bool score_blk = ks_blk || qs_blk;
    const int hl = wn >> 6;
    const int ppair = (wn >> 5) & 1;

    auto apply = [&](int r, int c, float v0, float v1) -> float {
        if (mode == GT_PRE) {
            if (c < 768) {
                g_F[(size_t)r * 768 + c] = v0 + bias[c];
                g_F[(size_t)r * 768 + c + 1] = v1 + bias[c + 1];
                return 0.f;
            }
            int head = (bx - 6) * 2 + hl;
            return lrelu_(v0 + bias[c]) * alpha[head * 128 + (c & 63)]
                 + lrelu_(v1 + bias[c + 1]) * alpha[head * 128 + (c & 63) + 1];
        } else if (mode == GT_KV) {
            if (c < 256) {
                int head = bx * 2 + hl;
                return lrelu_(v0 + bias[c]) * alpha[head * 128 + 64 + (c & 63)]
                     + lrelu_(v1 + bias[c + 1]) * alpha[head * 128 + 64 + (c & 63) + 1];
            }
            dst[(size_t)r * 256 + c - 256] = v0 + bias[c];
            dst[(size_t)r * 256 + c - 255] = v1 + bias[c + 1];
            return 0.f;
        } else if (mode == GT_ZR) {
            if (c < 256) {
                g_z[(size_t)r * 256 + c] = sigmoidf_(g_F[(size_t)r * 768 + c] + v0);
                g_z[(size_t)r * 256 + c + 1] = sigmoidf_(g_F[(size_t)r * 768 + c + 1] + v1);
            } else {
                int cc = c - 256;
                float rv0 = sigmoidf_(g_F[(size_t)r * 768 + 256 + cc] + v0) *
                            g_sumh[(size_t)r * 256 + cc];
                float rv1 = sigmoidf_(g_F[(size_t)r * 768 + 257 + cc] + v1) *
                            g_sumh[(size_t)r * 256 + cc + 1];
                g_rs16[(size_t)r * 256 + cc] = __float2half_rn(rv0);
                g_rs16[(size_t)r * 256 + cc + 1] = __float2half_rn(rv1);
            }
            return 0.f;
        } else {  // GT_FINAL
            float pre0 = tanhf(g_F[(size_t)r * 768 + 512 + c] + v0);
            float pre1 = tanhf(g_F[(size_t)r * 768 + 513 + c] + v1);
            float z0 = g_z[(size_t)r * 256 + c], z1 = g_z[(size_t)r * 256 + c + 1];
            float s0 = g_sumh[(size_t)r * 256 + c], s1 = g_sumh[(size_t)r * 256 + c + 1];
            float nh0 = (1.0f - z0) * s0 + z0 * pre0;
            float nh1 = (1.0f - z1) * s1 + z1 * pre1;
            if (r == 0) { nh0 = 0.0f; nh1 = 0.0f; }
            dst[(size_t)r * 256 + c] = nh0;
            dst[(size_t)r * 256 + c + 1] = nh1;
            g_h16[(size_t)r * 256 + c] = __float2half_rn(nh0);
            g_h16[(size_t)r * 256 + c + 1] = __float2half_rn(nh1);
            return 0.f;
        }
    };

    float red[4][2];
#pragma unroll
    for (int mt = 0; mt < 4; mt++) { red[mt][0] = 0.f; red[mt][1] = 0.f; }

#pragma unroll
    for (int mt = 0; mt < 4; mt++) {
#pragma unroll
        for (int nt = 0; nt < 4; nt++) {
            int r = row0 + wm + mt * 16 + (lane >> 2);
            int c = col0 + wn + nt * 8 + ((lane & 3) << 1);
            red[mt][0] += apply(r, c, acc[mt][nt][0], acc[mt][nt][1]);
            red[mt][1] += apply(r + 8, c, acc[mt][nt][2], acc[mt][nt][3]);
        }
    }

    if (score_blk) {
#pragma unroll
        for (int mt = 0; mt < 4; mt++) {
#pragma unroll
            for (int j = 0; j < 2; j++) {
                red[mt][j] += __shfl_xor_sync(0xffffffffu, red[mt][j], 1);
                red[mt][j] += __shfl_xor_sync(0xffffffffu, red[mt][j], 2);
            }
        }
        if ((lane & 3) == 0) {
            int rl = wm + (lane >> 2);
#pragma unroll
            for (int mt = 0; mt < 4; mt++) {
                int row = rl + mt * 16;
                scr[(row * 2 + hl) * 2 + ppair] = red[mt][0];
                scr[((row + 8) * 2 + hl) * 2 + ppair] = red[mt][1];
            }
        }
        __syncthreads();
        if (tid < 256) {
            int row = tid >> 1, h2 = tid & 1;
            float val = scr[(row * 2 + h2) * 2] + scr[(row * 2 + h2) * 2 + 1];
            if (ks_blk) g_ks[(row0 + row) * 4 + bx * 2 + h2] = val;
            else        g_qs[(row0 + row) * 4 + (bx - 6) * 2 + h2] = val;
        }
    }
}

// ---------------- attention: 1 warp per row ------------------------------------
// Mask: neighbor j is padding iff j == 0 (row 0 forced to zero every step;
// steps >= 1 rows generically nonzero; step 0 handled by rank-1 shortcut).
__global__ __launch_bounds__(256)
void attn_kernel(const int* __restrict__ bgraph, const float* __restrict__ abias) {
    __shared__ float w[8][NNB * HEADS];
    __shared__ int js[8][NNB];
    int warp = threadIdx.x >> 5, lane = threadIdx.x & 31;
    int n = blockIdx.x * 8 + warp;

    float s[HEADS];
    int j = 0;
    if (lane < NNB) {
        j = bgraph[n * NNB + lane];
        js[warp][lane] = j;
#pragma unroll
        for (int h = 0; h < HEADS; h++) {
            s[h] = g_qs[n * 4 + h] + g_ks[j * 4 + h] + abias[h];
            if (j == 0) s[h] = NEG_INF;
        }
    } else {
#pragma unroll
        for (int h = 0; h < HEADS; h++) s[h] = -2e18f;   // below any real/masked score
    }
    // full-warp softmax per head (inactive lanes contribute exp -> 0)
#pragma unroll
    for (int h = 0; h < HEADS; h++) {
        float mx = s[h];
        for (int d = 16; d; d >>= 1) mx = fmaxf(mx, __shfl_xor_sync(0xffffffffu, mx, d));
        float e = expf(s[h] - mx);
        float ssum = e;
        for (int d = 16; d; d >>= 1) ssum += __shfl_xor_sync(0xffffffffu, ssum, d);
        if (lane < NNB) w[warp][h * NNB + lane] = e / ssum;
    }
    __syncwarp();

    // weighted V gather: each lane handles 8 columns
#pragma unroll
    for (int k = 0; k < 8; k++) {
        int c = lane + 32 * k;
        int h = c >> 6;
        float acc = 0.f;
#pragma unroll
        for (int m = 0; m < NNB; m++)
            acc += w[warp][h * NNB + m] * g_V[(size_t)js[warp][m] * 256 + c];
        size_t idx = (size_t)n * H + c;
        g_sumh[idx] = acc;
        g_sh16[idx] = __float2half_rn(acc);
    }
}

// ---------------- launch -------------------------------------------------------
static void* symaddr(const void* s) {
    void* p = nullptr;
    cudaGetSymbolAddress(&p, s);
    return p;
}

extern "C" void kernel_launch(void* const* d_in, const int* in_sizes, int n_in,
                              void* d_out, int out_size) {
    const float* fmess = (const float*)d_in[0];
    const int*   bgraph = (const int*)d_in[1];
    const float* Wq = (const float*)d_in[2];
    const float* bq = (const float*)d_in[3];
    const float* Wk = (const float*)d_in[4];
    const float* bk = (const float*)d_in[5];
    const float* Wv = (const float*)d_in[6];
    const float* bv = (const float*)d_in[7];
    const float* alpha = (const float*)d_in[8];
    const float* abias = (const float*)d_in[9];
    const float* Wz = (const float*)d_in[10];
    const float* bz = (const float*)d_in[11];
    const float* Wr = (const float*)d_in[12];
    const float* Ur = (const float*)d_in[13];
    const float* bur = (const float*)d_in[14];
    const float* Wh = (const float*)d_in[15];
    const float* bh = (const float*)d_in[16];
    float* out = (float*)d_out;

    float* p_h = (float*)symaddr(g_h);
    float* p_V = (float*)symaddr(g_V);
    const __half* a_h16  = (const __half*)symaddr(g_h16);
    const __half* a_sh16 = (const __half*)symaddr(g_sh16);
    const __half* a_rs16 = (const __half*)symaddr(g_rs16);
    const __half* a_f16  = (const __half*)symaddr(g_f16);
    const __half* w_kv   = (const __half*)symaddr(g_Wkv16);
    const __half* w_zr   = (const __half*)symaddr(g_Wzr16);
    const __half* w_h2   = (const __half*)symaddr(g_Wh216);
    const __half* w_pr   = (const __half*)symaddr(g_Wpre16);
    const float* b_kv  = (const float*)symaddr(g_bkv);
    const float* b_pre = (const float*)symaddr(g_bpre);

    cudaFuncSetAttribute(gemm_mma, cudaFuncAttributeMaxDynamicSharedMemorySize, SMEM_DYN);

    // merged setup: pad + pack + bv_t (one launch)
    setup_all<<<PAD_BLOCKS + 64, 256>>>(fmess, Wq, bq, Wk, bk, Wv, bv,
                                        Wz, bz, Wr, Ur, bur, Wh, bh);

    // PRE: [F(768) | qscore] = fmess @ Wpre^T + bpre (qscore fused, blocks x>=6)
    gemm_mma<<<dim3(8, 128), 256, SMEM_DYN>>>(a_f16, w_pr, b_pre, alpha,
                                              KQ, GT_PRE, nullptr);

    // ---- step 0 (exact rank-1 shortcut: h=0 => sum_h = bv for every row) ----
    zr0_kernel<<<N_MSG * H / 256, 256>>>(bv);
    gemm_mma<<<dim3(2, 128), 256, SMEM_DYN>>>(a_rs16, w_h2, nullptr, nullptr,
                                              H, GT_FINAL, p_h);

    // ---- steps 1..DEPTH-1 ----
    for (int step = 1; step < DEPTH; step++) {
        // KV: blocks x<2 reduce kscore (K not stored); x>=2 store V
        gemm_mma<<<dim3(4, 128), 256, SMEM_DYN>>>(a_h16, w_kv, b_kv, alpha,
                                                  H, GT_KV, p_V);
        attn_kernel<<<N_MSG / 8, 256>>>(bgraph, abias);
        gemm_mma<<<dim3(4, 128), 256, SMEM_DYN>>>(a_sh16, w_zr, nullptr, nullptr,
                                                  H, GT_ZR, nullptr);
        gemm_mma<<<dim3(2, 128), 256, SMEM_DYN>>>(a_rs16, w_h2, nullptr, nullptr,
                                                  H, GT_FINAL,
                                                  step == DEPTH - 1 ? out : p_h);
    }
    (void)in_sizes; (void)n_in; (void)out_size;
}

// round 16
// speedup vs baseline: 1.8686x; 1.2308x over previous
#include <cuda_runtime.h>
#include <cuda_fp16.h>
#include <cstdint>

#define N_MSG 16384
#define NNB 10
#define IN_F 135
#define KQ 160            // padded fmess K (multiple of 32)
#define H 256
#define HEADS 4
#define DEPTH 5
#define NEG_INF -1e18f

// ---------------- state ------------------------------------------------------
__device__ float g_V[N_MSG * H];         // V only; K never materialized
__device__ float g_qs[N_MSG * HEADS];
__device__ float g_ks[N_MSG * HEADS];
__device__ float g_tzr[2 * H];           // step-0: bv @ [Wz2|Ur]^T
// fp16 state (half2-accessed)
__device__ __align__(16) __half g_F16[N_MSG * 3 * H];   // [Fz|Fr|Fh]
__device__ __align__(16) __half g_z16[N_MSG * H];
__device__ __align__(16) __half g_h16[N_MSG * H];
__device__ __align__(16) __half g_sh16[N_MSG * H];      // sum_h (attn out)
__device__ __align__(16) __half g_rs16[N_MSG * H];
__device__ __align__(16) __half g_f16[N_MSG * KQ];
__device__ __align__(16) __half g_Wkv16[512 * H];
__device__ __align__(16) __half g_Wzr16[512 * H];
__device__ __align__(16) __half g_Wh216[H * H];
__device__ __align__(16) __half g_Wpre16[1024 * KQ];
__device__ float g_bkv[512];
__device__ float g_bpre[1024];

// ---------------- helpers ----------------------------------------------------
__device__ __forceinline__ float sigmoidf_(float x) { return 1.0f / (1.0f + expf(-x)); }
__device__ __forceinline__ float lrelu_(float x) { return x >= 0.f ? x : 0.01f * x; }

__device__ __forceinline__ uint32_t smem_u32(const void* p) {
    uint32_t a;
    asm("{ .reg .u64 t; cvta.to.shared.u64 t, %1; cvt.u32.u64 %0, t; }" : "=r"(a) : "l"(p));
    return a;
}
__device__ __forceinline__ void ldsm_x4(uint32_t& r0, uint32_t& r1, uint32_t& r2,
                                        uint32_t& r3, uint32_t addr) {
    asm volatile("ldmatrix.sync.aligned.m8n8.x4.shared.b16 {%0,%1,%2,%3}, [%4];"
                 : "=r"(r0), "=r"(r1), "=r"(r2), "=r"(r3) : "r"(addr));
}
__device__ __forceinline__ void mma16816(float* d, const uint32_t* a, const uint32_t* b) {
    asm volatile(
        "mma.sync.aligned.m16n8k16.row.col.f32.f16.f16.f32 "
        "{%0,%1,%2,%3}, {%4,%5,%6,%7}, {%8,%9}, {%0,%1,%2,%3};"
        : "+f"(d[0]), "+f"(d[1]), "+f"(d[2]), "+f"(d[3])
        : "r"(a[0]), "r"(a[1]), "r"(a[2]), "r"(a[3]), "r"(b[0]), "r"(b[1]));
}
#define CP16(dst, src) \
    asm volatile("cp.async.cg.shared.global [%0], [%1], 16;" :: "r"(dst), "l"(src))
#define CP_COMMIT() asm volatile("cp.async.commit_group;" ::: "memory")
#define CP_WAIT(n)  asm volatile("cp.async.wait_group %0;" :: "n"(n) : "memory")

// half2 load/store helpers
__device__ __forceinline__ void st_h2(__half* p, float a, float b) {
    *reinterpret_cast<__half2*>(p) = __floats2half2_rn(a, b);
}
__device__ __forceinline__ float2 ld_h2(const __half* p) {
    return __half22float2(*reinterpret_cast<const __half2*>(p));
}

// ---------------- merged setup: pad fmess + pack weights + bv_t --------------
#define PAD_BLOCKS ((N_MSG * KQ) / 256)   // 10240
__global__ void setup_all(const float* __restrict__ fmess,
                          const float* __restrict__ Wq, const float* __restrict__ bq,
                          const float* __restrict__ Wk, const float* __restrict__ bk,
                          const float* __restrict__ Wv, const float* __restrict__ bv,
                          const float* __restrict__ Wz, const float* __restrict__ bz,
                          const float* __restrict__ Wr, const float* __restrict__ Ur,
                          const float* __restrict__ bur,
                          const float* __restrict__ Wh, const float* __restrict__ bh) {
    const int WIDE = IN_F + H;  // 391
    int b = blockIdx.x;
    if (b >= PAD_BLOCKS) {
        int o = (b - PAD_BLOCKS) * 8 + (threadIdx.x >> 5);
        int lane = threadIdx.x & 31;
        float s = 0.f;
#pragma unroll
        for (int t = 0; t < 8; t++) {
            int k = lane + 32 * t;
            float w = (o < 256) ? Wz[o * WIDE + IN_F + k] : Ur[(o - 256) * H + k];
            s += bv[k] * w;
        }
        for (int d = 16; d; d >>= 1) s += __shfl_xor_sync(0xffffffffu, s, d);
        if (lane == 0) g_tzr[o] = s;
        return;
    }
    int i = b * 256 + threadIdx.x;
    {
        int n = i / KQ, c = i % KQ;
        float x = (c < IN_F) ? fmess[n * IN_F + c] : 0.0f;
        g_f16[i] = __float2half_rn(x);
    }
    if (i < 512 * H) {
        int n = i / H, k = i % H;
        float kv = (n < H) ? Wk[n * H + k] : Wv[(n - H) * H + k];
        g_Wkv16[i] = __float2half_rn(kv);
        float zr = (n < H) ? Wz[n * WIDE + IN_F + k] : Ur[(n - H) * H + k];
        g_Wzr16[i] = __float2half_rn(zr);
    }
    if (i < H * H) {
        int n = i / H, k = i % H;
        g_Wh216[i] = __float2half_rn(Wh[n * WIDE + IN_F + k]);
    }
    if (i < 1024 * KQ) {
        int n = i / KQ, k = i % KQ;
        float v = 0.0f;
        if (k < IN_F) {
            if (n < 256) v = Wz[n * WIDE + k];
            else if (n < 512) v = Wr[(n - 256) * IN_F + k];
            else if (n < 768) v = Wh[(n - 512) * WIDE + k];
            else v = Wq[(n - 768) * IN_F + k];
        }
        g_Wpre16[i] = __float2half_rn(v);
    }
    if (i < 512) g_bkv[i] = (i < 256) ? bk[i] : bv[i - 256];
    if (i < 1024) {
        float bb = (i < 256) ? bz[i] : (i < 512) ? bur[i - 256]
                 : (i < 768) ? bh[i - 512] : bq[i - 768];
        g_bpre[i] = bb;
    }
}

// ---------------- step-0 elementwise -----------------------------------------
__global__ void zr0_kernel(const float* __restrict__ bv) {
    int i2 = blockIdx.x * blockDim.x + threadIdx.x;   // over N*H/2 (pairs)
    int i = i2 * 2;
    int n = i >> 8, c = i & 255;
    float b0 = bv[c], b1 = bv[c + 1];
    st_h2(&g_sh16[i], b0, b1);
    float2 fz = ld_h2(&g_F16[(size_t)n * 768 + c]);
    st_h2(&g_z16[i], sigmoidf_(fz.x + g_tzr[c]), sigmoidf_(fz.y + g_tzr[c + 1]));
    float2 fr = ld_h2(&g_F16[(size_t)n * 768 + 256 + c]);
    st_h2(&g_rs16[i], sigmoidf_(fr.x + g_tzr[256 + c]) * b0,
                      sigmoidf_(fr.y + g_tzr[257 + c]) * b1);
}

// ---------------- mma.sync GEMM: 128x128 tile ---------------------------------
#define GT_PRE 0
#define GT_KV 1
#define GT_ZR 2
#define GT_FINAL 3
#define STR 40
#define STAGEB (128 * STR * 2)
#define SMEM_DYN (8 * STAGEB)

__global__ __launch_bounds__(256, 2)
void gemm_mma(const __half* __restrict__ Aw, const __half* __restrict__ Bw,
              const float* __restrict__ bias, const float* __restrict__ alpha,
              int Kp, int mode, float* __restrict__ dst) {
    extern __shared__ __half dsm[];
    const uint32_t sA0 = smem_u32(dsm);
    const uint32_t sB0 = sA0 + 4 * STAGEB;

    const int tid = threadIdx.x, lane = tid & 31, wid = tid >> 5;
    const int wm = (wid & 1) * 64, wn = (wid >> 1) * 32;
    const int bx = blockIdx.x;
    const int row0 = blockIdx.y * 128, col0 = bx * 128;

    const int arow = wm + (lane & 15), ak = (lane >> 4) << 3;
    const int g = lane >> 3;
    const int brow = wn + ((g >> 1) << 3) + (lane & 7), bk = (g & 1) << 3;
    const uint32_t aoff_l = (uint32_t)(arow * STR + ak) * 2;
    const uint32_t boff_l = (uint32_t)(brow * STR + bk) * 2;

    const int NC = Kp >> 5;

    auto issue = [&](int c) {
        int kk = c << 5;
        const uint32_t abase = sA0 + (uint32_t)(c & 3) * STAGEB;
        const uint32_t bbase = sB0 + (uint32_t)(c & 3) * STAGEB;
#pragma unroll
        for (int i = 0; i < 2; i++) {
            int t2 = tid + (i << 8);
            int row = t2 >> 2, coli = (t2 & 3) << 3;
            uint32_t so = (uint32_t)(row * STR + coli) * 2;
            CP16(abase + so, Aw + (size_t)(row0 + row) * Kp + kk + coli);
            CP16(bbase + so, Bw + (size_t)(col0 + row) * Kp + kk + coli);
        }
        CP_COMMIT();
    };

    float acc[4][4][4];
#pragma unroll
    for (int i = 0; i < 4; i++)
#pragma unroll
        for (int j = 0; j < 4; j++)
#pragma unroll
            for (int q = 0; q < 4; q++) acc[i][j][q] = 0.f;

    issue(0); issue(1); issue(2);

    for (int c = 0; c < NC; c++) {
        const int allowed = NC - 1 - c;
        if (allowed >= 2)      CP_WAIT(2);
        else if (allowed == 1) CP_WAIT(1);
        else                   CP_WAIT(0);
        __syncthreads();
        if (c + 3 < NC) issue(c + 3);

        const uint32_t abase = sA0 + (uint32_t)(c & 3) * STAGEB + aoff_l;
        const uint32_t bbase = sB0 + (uint32_t)(c & 3) * STAGEB + boff_l;
#pragma unroll
        for (int kk2 = 0; kk2 < 2; kk2++) {
            uint32_t a[4][4], bf[4][2];
#pragma unroll
            for (int mt = 0; mt < 4; mt++)
                ldsm_x4(a[mt][0], a[mt][1], a[mt][2], a[mt][3],
                        abase + mt * 16 * STR * 2 + kk2 * 32);
#pragma unroll
            for (int np = 0; np < 2; np++)
                ldsm_x4(bf[2 * np][0], bf[2 * np][1], bf[2 * np + 1][0], bf[2 * np + 1][1],
                        bbase + np * 16 * STR * 2 + kk2 * 32);
#pragma unroll
            for (int mt = 0; mt < 4; mt++)
#pragma unroll
                for (int nt = 0; nt < 4; nt++)
                    mma16816(acc[mt][nt], a[mt], bf[nt]);
        }
    }

    // ---------------- fused epilogue (atomic-free; fp16 state) ----------------
    __syncthreads();
    float* scr = reinterpret_cast<float*>(dsm);
    const bool ks_blk = (mode == GT_KV && bx < 2);
    const bool qs_blk = (mode == GT_PRE && bx >= 6);
    const bool score_blk = ks_blk || qs_blk;
    const int hl = wn >> 6;
    const int ppair = (wn >> 5) & 1;

    auto apply = [&](int r, int c, float v0, float v1) -> float {
        if (mode == GT_PRE) {
            if (c < 768) {
                st_h2(&g_F16[(size_t)r * 768 + c], v0 + bias[c], v1 + bias[c + 1]);
                return 0.f;
            }
            int head = (bx - 6) * 2 + hl;
            return lrelu_(v0 + bias[c]) * alpha[head * 128 + (c & 63)]
                 + lrelu_(v1 + bias[c + 1]) * alpha[head * 128 + (c & 63) + 1];
        } else if (mode == GT_KV) {
            if (c < 256) {
                int head = bx * 2 + hl;
                return lrelu_(v0 + bias[c]) * alpha[head * 128 + 64 + (c & 63)]
                     + lrelu_(v1 + bias[c + 1]) * alpha[head * 128 + 64 + (c & 63) + 1];
            }
            dst[(size_t)r * 256 + c - 256] = v0 + bias[c];
            dst[(size_t)r * 256 + c - 255] = v1 + bias[c + 1];
            return 0.f;
        } else if (mode == GT_ZR) {
            if (c < 256) {
                float2 f = ld_h2(&g_F16[(size_t)r * 768 + c]);
                st_h2(&g_z16[(size_t)r * 256 + c],
                      sigmoidf_(f.x + v0), sigmoidf_(f.y + v1));
            } else {
                int cc = c - 256;
                float2 f = ld_h2(&g_F16[(size_t)r * 768 + 256 + cc]);
                float2 s = ld_h2(&g_sh16[(size_t)r * 256 + cc]);
                st_h2(&g_rs16[(size_t)r * 256 + cc],
                      sigmoidf_(f.x + v0) * s.x, sigmoidf_(f.y + v1) * s.y);
            }
            return 0.f;
        } else {  // GT_FINAL
            float2 f = ld_h2(&g_F16[(size_t)r * 768 + 512 + c]);
            float2 z = ld_h2(&g_z16[(size_t)r * 256 + c]);
            float2 s = ld_h2(&g_sh16[(size_t)r * 256 + c]);
            float nh0 = (1.0f - z.x) * s.x + z.x * tanhf(f.x + v0);
            float nh1 = (1.0f - z.y) * s.y + z.y * tanhf(f.y + v1);
            if (r == 0) { nh0 = 0.0f; nh1 = 0.0f; }
            if (dst) {
                dst[(size_t)r * 256 + c] = nh0;
                dst[(size_t)r * 256 + c + 1] = nh1;
            }
            st_h2(&g_h16[(size_t)r * 256 + c], nh0, nh1);
            return 0.f;
        }
    };

    float red[4][2];
#pragma unroll
    for (int mt = 0; mt < 4; mt++) { red[mt][0] = 0.f; red[mt][1] = 0.f; }

#pragma unroll
    for (int mt = 0; mt < 4; mt++) {
#pragma unroll
        for (int nt = 0; nt < 4; nt++) {
            int r = row0 + wm + mt * 16 + (lane >> 2);
            int c = col0 + wn + nt * 8 + ((lane & 3) << 1);
            red[mt][0] += apply(r, c, acc[mt][nt][0], acc[mt][nt][1]);
            red[mt][1] += apply(r + 8, c, acc[mt][nt][2], acc[mt][nt][3]);
        }
    }

    if (score_blk) {
#pragma unroll
        for (int mt = 0; mt < 4; mt++) {
#pragma unroll
            for (int j = 0; j < 2; j++) {
                red[mt][j] += __shfl_xor_sync(0xffffffffu, red[mt][j], 1);
                red[mt][j] += __shfl_xor_sync(0xffffffffu, red[mt][j], 2);
            }
        }
        if ((lane & 3) == 0) {
            int rl = wm + (lane >> 2);
#pragma unroll
            for (int mt = 0; mt < 4; mt++) {
                int row = rl + mt * 16;
                scr[(row * 2 + hl) * 2 + ppair] = red[mt][0];
                scr[((row + 8) * 2 + hl) * 2 + ppair] = red[mt][1];
            }
        }
        __syncthreads();
        if (tid < 256) {
            int row = tid >> 1, h2 = tid & 1;
            float val = scr[(row * 2 + h2) * 2] + scr[(row * 2 + h2) * 2 + 1];
            if (ks_blk) g_ks[(row0 + row) * 4 + bx * 2 + h2] = val;
            else        g_qs[(row0 + row) * 4 + (bx - 6) * 2 + h2] = val;
        }
    }
}

// ---------------- attention: 1 warp per row ------------------------------------
__global__ __launch_bounds__(256)
void attn_kernel(const int* __restrict__ bgraph, const float* __restrict__ abias) {
    __shared__ float w[8][NNB * HEADS];
    __shared__ int js[8][NNB];
    int warp = threadIdx.x >> 5, lane = threadIdx.x & 31;
    int n = blockIdx.x * 8 + warp;

    float s[HEADS];
    if (lane < NNB) {
        int j = bgraph[n * NNB + lane];
        js[warp][lane] = j;
#pragma unroll
        for (int h = 0; h < HEADS; h++) {
            s[h] = g_qs[n * 4 + h] + g_ks[j * 4 + h] + abias[h];
            if (j == 0) s[h] = NEG_INF;
        }
    } else {
#pragma unroll
        for (int h = 0; h < HEADS; h++) s[h] = -2e18f;
    }
#pragma unroll
    for (int h = 0; h < HEADS; h++) {
        float mx = s[h];
        for (int d = 16; d; d >>= 1) mx = fmaxf(mx, __shfl_xor_sync(0xffffffffu, mx, d));
        float e = expf(s[h] - mx);
        float ssum = e;
        for (int d = 16; d; d >>= 1) ssum += __shfl_xor_sync(0xffffffffu, ssum, d);
        if (lane < NNB) w[warp][h * NNB + lane] = e / ssum;
    }
    __syncwarp();

#pragma unroll
    for (int k = 0; k < 4; k++) {
        int c = (lane + 32 * k) * 2;    // pair of columns
        int h = c >> 6;
        float a0 = 0.f, a1 = 0.f;
#pragma unroll
        for (int m = 0; m < NNB; m++) {
            float ww = w[warp][h * NNB + m];
            const float* vp = &g_V[(size_t)js[warp][m] * 256 + c];
            a0 += ww * vp[0];
            a1 += ww * vp[1];
        }
        st_h2(&g_sh16[(size_t)n * H + c], a0, a1);
    }
}

// ---------------- launch -------------------------------------------------------
static void* symaddr(const void* s) {
    void* p = nullptr;
    cudaGetSymbolAddress(&p, s);
    return p;
}

extern "C" void kernel_launch(void* const* d_in, const int* in_sizes, int n_in,
                              void* d_out, int out_size) {
    const float* fmess = (const float*)d_in[0];
    const int*   bgraph = (const int*)d_in[1];
    const float* Wq = (const float*)d_in[2];
    const float* bq = (const float*)d_in[3];
    const float* Wk = (const float*)d_in[4];
    const float* bk = (const float*)d_in[5];
    const float* Wv = (const float*)d_in[6];
    const float* bv = (const float*)d_in[7];
    const float* alpha = (const float*)d_in[8];
    const float* abias = (const float*)d_in[9];
    const float* Wz = (const float*)d_in[10];
    const float* bz = (const float*)d_in[11];
    const float* Wr = (const float*)d_in[12];
    const float* Ur = (const float*)d_in[13];
    const float* bur = (const float*)d_in[14];
    const float* Wh = (const float*)d_in[15];
    const float* bh = (const float*)d_in[16];
    float* out = (float*)d_out;

    float* p_V = (float*)symaddr(g_V);
    const __half* a_h16  = (const __half*)symaddr(g_h16);
    const __half* a_sh16 = (const __half*)symaddr(g_sh16);
    const __half* a_rs16 = (const __half*)symaddr(g_rs16);
    const __half* a_f16  = (const __half*)symaddr(g_f16);
    const __half* w_kv   = (const __half*)symaddr(g_Wkv16);
    const __half* w_zr   = (const __half*)symaddr(g_Wzr16);
    const __half* w_h2   = (const __half*)symaddr(g_Wh216);
    const __half* w_pr   = (const __half*)symaddr(g_Wpre16);
    const float* b_kv  = (const float*)symaddr(g_bkv);
    const float* b_pre = (const float*)symaddr(g_bpre);

    cudaFuncSetAttribute(gemm_mma, cudaFuncAttributeMaxDynamicSharedMemorySize, SMEM_DYN);

    setup_all<<<PAD_BLOCKS + 64, 256>>>(fmess, Wq, bq, Wk, bk, Wv, bv,
                                        Wz, bz, Wr, Ur, bur, Wh, bh);

    // PRE: [F(768) | qscore] = fmess @ Wpre^T + bpre
    gemm_mma<<<dim3(8, 128), 256, SMEM_DYN>>>(a_f16, w_pr, b_pre, alpha,
                                              KQ, GT_PRE, nullptr);

    // ---- step 0 (exact rank-1 shortcut) ----
    zr0_kernel<<<N_MSG * H / 512, 256>>>(bv);
    gemm_mma<<<dim3(2, 128), 256, SMEM_DYN>>>(a_rs16, w_h2, nullptr, nullptr,
                                              H, GT_FINAL, nullptr);

    // ---- steps 1..DEPTH-1 ----
    for (int step = 1; step < DEPTH; step++) {
        gemm_mma<<<dim3(4, 128), 256, SMEM_DYN>>>(a_h16, w_kv, b_kv, alpha,
                                                  H, GT_KV, p_V);
        attn_kernel<<<N_MSG / 8, 256>>>(bgraph, abias);
        gemm_mma<<<dim3(4, 128), 256, SMEM_DYN>>>(a_sh16, w_zr, nullptr, nullptr,
                                                  H, GT_ZR, nullptr);
        gemm_mma<<<dim3(2, 128), 256, SMEM_DYN>>>(a_rs16, w_h2, nullptr, nullptr,
                                                  H, GT_FINAL,
                                                  step == DEPTH - 1 ? out : nullptr);
    }
    (void)in_sizes; (void)n_in; (void)out_size;
}

// round 17
// speedup vs baseline: 2.0267x; 1.0846x over previous
#include <cuda_runtime.h>
#include <cuda_fp16.h>
#include <cstdint>

#define N_MSG 16384
#define NNB 10
#define IN_F 135
#define KQ 160            // padded fmess K (multiple of 32)
#define H 256
#define HEADS 4
#define DEPTH 5
#define NEG_INF -1e18f

// ---------------- state ------------------------------------------------------
__device__ float g_qs[N_MSG * HEADS];
__device__ float g_ks[N_MSG * HEADS];
__device__ float g_tzr[2 * H];           // step-0: bv @ [Wz2|Ur]^T
// fp16 state (half2-accessed)
__device__ __align__(16) __half g_V16[N_MSG * H];       // V (fp16)
__device__ __align__(16) __half g_F16[N_MSG * 3 * H];   // [Fz|Fr|Fh]
__device__ __align__(16) __half g_z16[N_MSG * H];
__device__ __align__(16) __half g_h16[N_MSG * H];
__device__ __align__(16) __half g_sh16[N_MSG * H];      // sum_h (attn out)
__device__ __align__(16) __half g_rs16[N_MSG * H];
__device__ __align__(16) __half g_f16[N_MSG * KQ];
__device__ __align__(16) __half g_Wkv16[512 * H];
__device__ __align__(16) __half g_Wzr16[512 * H];
__device__ __align__(16) __half g_Wh216[H * H];
__device__ __align__(16) __half g_Wpre16[1024 * KQ];
__device__ float g_bkv[512];
__device__ float g_bpre[1024];

// ---------------- helpers ----------------------------------------------------
__device__ __forceinline__ float sigmoidf_(float x) { return 1.0f / (1.0f + expf(-x)); }
__device__ __forceinline__ float lrelu_(float x) { return x >= 0.f ? x : 0.01f * x; }

__device__ __forceinline__ uint32_t smem_u32(const void* p) {
    uint32_t a;
    asm("{ .reg .u64 t; cvta.to.shared.u64 t, %1; cvt.u32.u64 %0, t; }" : "=r"(a) : "l"(p));
    return a;
}
__device__ __forceinline__ void ldsm_x4(uint32_t& r0, uint32_t& r1, uint32_t& r2,
                                        uint32_t& r3, uint32_t addr) {
    asm volatile("ldmatrix.sync.aligned.m8n8.x4.shared.b16 {%0,%1,%2,%3}, [%4];"
                 : "=r"(r0), "=r"(r1), "=r"(r2), "=r"(r3) : "r"(addr));
}
__device__ __forceinline__ void mma16816(float* d, const uint32_t* a, const uint32_t* b) {
    asm volatile(
        "mma.sync.aligned.m16n8k16.row.col.f32.f16.f16.f32 "
        "{%0,%1,%2,%3}, {%4,%5,%6,%7}, {%8,%9}, {%0,%1,%2,%3};"
        : "+f"(d[0]), "+f"(d[1]), "+f"(d[2]), "+f"(d[3])
        : "r"(a[0]), "r"(a[1]), "r"(a[2]), "r"(a[3]), "r"(b[0]), "r"(b[1]));
}
#define CP16(dst, src) \
    asm volatile("cp.async.cg.shared.global [%0], [%1], 16;" :: "r"(dst), "l"(src))
#define CP_COMMIT() asm volatile("cp.async.commit_group;" ::: "memory")
#define CP_WAIT(n)  asm volatile("cp.async.wait_group %0;" :: "n"(n) : "memory")

__device__ __forceinline__ void st_h2(__half* p, float a, float b) {
    *reinterpret_cast<__half2*>(p) = __floats2half2_rn(a, b);
}
__device__ __forceinline__ float2 ld_h2(const __half* p) {
    return __half22float2(*reinterpret_cast<const __half2*>(p));
}

// ---------------- merged setup: pad fmess + pack weights + bv_t --------------
#define PAD_BLOCKS ((N_MSG * KQ) / 256)   // 10240
__global__ void setup_all(const float* __restrict__ fmess,
                          const float* __restrict__ Wq, const float* __restrict__ bq,
                          const float* __restrict__ Wk, const float* __restrict__ bk,
                          const float* __restrict__ Wv, const float* __restrict__ bv,
                          const float* __restrict__ Wz, const float* __restrict__ bz,
                          const float* __restrict__ Wr, const float* __restrict__ Ur,
                          const float* __restrict__ bur,
                          const float* __restrict__ Wh, const float* __restrict__ bh) {
    const int WIDE = IN_F + H;  // 391
    int b = blockIdx.x;
    if (b >= PAD_BLOCKS) {
        int o = (b - PAD_BLOCKS) * 8 + (threadIdx.x >> 5);
        int lane = threadIdx.x & 31;
        float s = 0.f;
#pragma unroll
        for (int t = 0; t < 8; t++) {
            int k = lane + 32 * t;
            float w = (o < 256) ? Wz[o * WIDE + IN_F + k] : Ur[(o - 256) * H + k];
            s += bv[k] * w;
        }
        for (int d = 16; d; d >>= 1) s += __shfl_xor_sync(0xffffffffu, s, d);
        if (lane == 0) g_tzr[o] = s;
        return;
    }
    int i = b * 256 + threadIdx.x;
    {
        int n = i / KQ, c = i % KQ;
        float x = (c < IN_F) ? fmess[n * IN_F + c] : 0.0f;
        g_f16[i] = __float2half_rn(x);
    }
    if (i < 512 * H) {
        int n = i / H, k = i % H;
        float kv = (n < H) ? Wk[n * H + k] : Wv[(n - H) * H + k];
        g_Wkv16[i] = __float2half_rn(kv);
        float zr = (n < H) ? Wz[n * WIDE + IN_F + k] : Ur[(n - H) * H + k];
        g_Wzr16[i] = __float2half_rn(zr);
    }
    if (i < H * H) {
        int n = i / H, k = i % H;
        g_Wh216[i] = __float2half_rn(Wh[n * WIDE + IN_F + k]);
    }
    if (i < 1024 * KQ) {
        int n = i / KQ, k = i % KQ;
        float v = 0.0f;
        if (k < IN_F) {
            if (n < 256) v = Wz[n * WIDE + k];
            else if (n < 512) v = Wr[(n - 256) * IN_F + k];
            else if (n < 768) v = Wh[(n - 512) * WIDE + k];
            else v = Wq[(n - 768) * IN_F + k];
        }
        g_Wpre16[i] = __float2half_rn(v);
    }
    if (i < 512) g_bkv[i] = (i < 256) ? bk[i] : bv[i - 256];
    if (i < 1024) {
        float bb = (i < 256) ? bz[i] : (i < 512) ? bur[i - 256]
                 : (i < 768) ? bh[i - 512] : bq[i - 768];
        g_bpre[i] = bb;
    }
}

// ---------------- step-0 elementwise -----------------------------------------
__global__ void zr0_kernel(const float* __restrict__ bv) {
    int i2 = blockIdx.x * blockDim.x + threadIdx.x;   // over N*H/2 (pairs)
    int i = i2 * 2;
    int n = i >> 8, c = i & 255;
    float b0 = bv[c], b1 = bv[c + 1];
    st_h2(&g_sh16[i], b0, b1);
    float2 fz = ld_h2(&g_F16[(size_t)n * 768 + c]);
    st_h2(&g_z16[i], sigmoidf_(fz.x + g_tzr[c]), sigmoidf_(fz.y + g_tzr[c + 1]));
    float2 fr = ld_h2(&g_F16[(size_t)n * 768 + 256 + c]);
    st_h2(&g_rs16[i], sigmoidf_(fr.x + g_tzr[256 + c]) * b0,
                      sigmoidf_(fr.y + g_tzr[257 + c]) * b1);
}

// ---------------- mma.sync GEMM: 128x128 tile ---------------------------------
#define GT_PRE 0
#define GT_KV 1
#define GT_ZR 2
#define GT_FINAL 3
#define STR 40
#define STAGEB (128 * STR * 2)
#define SMEM_DYN (8 * STAGEB)

__global__ __launch_bounds__(256, 2)
void gemm_mma(const __half* __restrict__ Aw, const __half* __restrict__ Bw,
              const float* __restrict__ bias, const float* __restrict__ alpha,
              int Kp, int mode, float* __restrict__ dst) {
    extern __shared__ __half dsm[];
    const uint32_t sA0 = smem_u32(dsm);
    const uint32_t sB0 = sA0 + 4 * STAGEB;

    const int tid = threadIdx.x, lane = tid & 31, wid = tid >> 5;
    const int wm = (wid & 1) * 64, wn = (wid >> 1) * 32;
    const int bx = blockIdx.x;
    const int row0 = blockIdx.y * 128, col0 = bx * 128;

    const int arow = wm + (lane & 15), ak = (lane >> 4) << 3;
    const int g = lane >> 3;
    const int brow = wn + ((g >> 1) << 3) + (lane & 7), bk = (g & 1) << 3;
    const uint32_t aoff_l = (uint32_t)(arow * STR + ak) * 2;
    const uint32_t boff_l = (uint32_t)(brow * STR + bk) * 2;

    const int NC = Kp >> 5;

    auto issue = [&](int c) {
        int kk = c << 5;
        const uint32_t abase = sA0 + (uint32_t)(c & 3) * STAGEB;
        const uint32_t bbase = sB0 + (uint32_t)(c & 3) * STAGEB;
#pragma unroll
        for (int i = 0; i < 2; i++) {
            int t2 = tid + (i << 8);
            int row = t2 >> 2, coli = (t2 & 3) << 3;
            uint32_t so = (uint32_t)(row * STR + coli) * 2;
            CP16(abase + so, Aw + (size_t)(row0 + row) * Kp + kk + coli);
            CP16(bbase + so, Bw + (size_t)(col0 + row) * Kp + kk + coli);
        }
        CP_COMMIT();
    };

    float acc[4][4][4];
#pragma unroll
    for (int i = 0; i < 4; i++)
#pragma unroll
        for (int j = 0; j < 4; j++)
#pragma unroll
            for (int q = 0; q < 4; q++) acc[i][j][q] = 0.f;

    issue(0); issue(1); issue(2);

    for (int c = 0; c < NC; c++) {
        const int allowed = NC - 1 - c;
        if (allowed >= 2)      CP_WAIT(2);
        else if (allowed == 1) CP_WAIT(1);
        else                   CP_WAIT(0);
        __syncthreads();
        if (c + 3 < NC) issue(c + 3);

        const uint32_t abase = sA0 + (uint32_t)(c & 3) * STAGEB + aoff_l;
        const uint32_t bbase = sB0 + (uint32_t)(c & 3) * STAGEB + boff_l;
#pragma unroll
        for (int kk2 = 0; kk2 < 2; kk2++) {
            uint32_t a[4][4], bf[4][2];
#pragma unroll
            for (int mt = 0; mt < 4; mt++)
                ldsm_x4(a[mt][0], a[mt][1], a[mt][2], a[mt][3],
                        abase + mt * 16 * STR * 2 + kk2 * 32);
#pragma unroll
            for (int np = 0; np < 2; np++)
                ldsm_x4(bf[2 * np][0], bf[2 * np][1], bf[2 * np + 1][0], bf[2 * np + 1][1],
                        bbase + np * 16 * STR * 2 + kk2 * 32);
#pragma unroll
            for (int mt = 0; mt < 4; mt++)
#pragma unroll
                for (int nt = 0; nt < 4; nt++)
                    mma16816(acc[mt][nt], a[mt], bf[nt]);
        }
    }

    // ---------------- fused epilogue (atomic-free; fp16 state) ----------------
    __syncthreads();
    float* scr = reinterpret_cast<float*>(dsm);
    const bool ks_blk = (mode == GT_KV && bx < 2);
    const bool qs_blk = (mode == GT_PRE && bx >= 6);
    const bool score_blk = ks_blk || qs_blk;
    const int hl = wn >> 6;
    const int ppair = (wn >> 5) & 1;

    auto apply = [&](int r, int c, float v0, float v1) -> float {
        if (mode == GT_PRE) {
            if (c < 768) {
                st_h2(&g_F16[(size_t)r * 768 + c], v0 + bias[c], v1 + bias[c + 1]);
                return 0.f;
            }
            int head = (bx - 6) * 2 + hl;
            return lrelu_(v0 + bias[c]) * alpha[head * 128 + (c & 63)]
                 + lrelu_(v1 + bias[c + 1]) * alpha[head * 128 + (c & 63) + 1];
        } else if (mode == GT_KV) {
            if (c < 256) {
                int head = bx * 2 + hl;
                return lrelu_(v0 + bias[c]) * alpha[head * 128 + 64 + (c & 63)]
                     + lrelu_(v1 + bias[c + 1]) * alpha[head * 128 + 64 + (c & 63) + 1];
            }
            st_h2(&g_V16[(size_t)r * 256 + c - 256], v0 + bias[c], v1 + bias[c + 1]);
            return 0.f;
        } else if (mode == GT_ZR) {
            if (c < 256) {
                float2 f = ld_h2(&g_F16[(size_t)r * 768 + c]);
                st_h2(&g_z16[(size_t)r * 256 + c],
                      sigmoidf_(f.x + v0), sigmoidf_(f.y + v1));
            } else {
                int cc = c - 256;
                float2 f = ld_h2(&g_F16[(size_t)r * 768 + 256 + cc]);
                float2 s = ld_h2(&g_sh16[(size_t)r * 256 + cc]);
                st_h2(&g_rs16[(size_t)r * 256 + cc],
                      sigmoidf_(f.x + v0) * s.x, sigmoidf_(f.y + v1) * s.y);
            }
            return 0.f;
        } else {  // GT_FINAL
            float2 f = ld_h2(&g_F16[(size_t)r * 768 + 512 + c]);
            float2 z = ld_h2(&g_z16[(size_t)r * 256 + c]);
            float2 s = ld_h2(&g_sh16[(size_t)r * 256 + c]);
            float nh0 = (1.0f - z.x) * s.x + z.x * tanhf(f.x + v0);
            float nh1 = (1.0f - z.y) * s.y + z.y * tanhf(f.y + v1);
            if (r == 0) { nh0 = 0.0f; nh1 = 0.0f; }
            if (dst) {
                dst[(size_t)r * 256 + c] = nh0;
                dst[(size_t)r * 256 + c + 1] = nh1;
            }
            st_h2(&g_h16[(size_t)r * 256 + c], nh0, nh1);
            return 0.f;
        }
    };

    float red[4][2];
#pragma unroll
    for (int mt = 0; mt < 4; mt++) { red[mt][0] = 0.f; red[mt][1] = 0.f; }

#pragma unroll
    for (int mt = 0; mt < 4; mt++) {
#pragma unroll
        for (int nt = 0; nt < 4; nt++) {
            int r = row0 + wm + mt * 16 + (lane >> 2);
            int c = col0 + wn + nt * 8 + ((lane & 3) << 1);
            red[mt][0] += apply(r, c, acc[mt][nt][0], acc[mt][nt][1]);
            red[mt][1] += apply(r + 8, c, acc[mt][nt][2], acc[mt][nt][3]);
        }
    }

    if (score_blk) {
#pragma unroll
        for (int mt = 0; mt < 4; mt++) {
#pragma unroll
            for (int j = 0; j < 2; j++) {
                red[mt][j] += __shfl_xor_sync(0xffffffffu, red[mt][j], 1);
                red[mt][j] += __shfl_xor_sync(0xffffffffu, red[mt][j], 2);
            }
        }
        if ((lane & 3) == 0) {
            int rl = wm + (lane >> 2);
#pragma unroll
            for (int mt = 0; mt < 4; mt++) {
                int row = rl + mt * 16;
                scr[(row * 2 + hl) * 2 + ppair] = red[mt][0];
                scr[((row + 8) * 2 + hl) * 2 + ppair] = red[mt][1];
            }
        }
        __syncthreads();
        if (tid < 256) {
            int row = tid >> 1, h2 = tid & 1;
            float val = scr[(row * 2 + h2) * 2] + scr[(row * 2 + h2) * 2 + 1];
            if (ks_blk) g_ks[(row0 + row) * 4 + bx * 2 + h2] = val;
            else        g_qs[(row0 + row) * 4 + (bx - 6) * 2 + h2] = val;
        }
    }
}

// ---------------- attention: 1 warp per row, vectorized fp16 V gather ----------
__global__ __launch_bounds__(256)
void attn_kernel(const int* __restrict__ bgraph, const float* __restrict__ abias) {
    __shared__ float w[8][NNB * HEADS];
    __shared__ int js[8][NNB];
    int warp = threadIdx.x >> 5, lane = threadIdx.x & 31;
    int n = blockIdx.x * 8 + warp;

    float s[HEADS];
    if (lane < NNB) {
        int j = bgraph[n * NNB + lane];
        js[warp][lane] = j;
#pragma unroll
        for (int h = 0; h < HEADS; h++) {
            s[h] = g_qs[n * 4 + h] + g_ks[j * 4 + h] + abias[h];
            if (j == 0) s[h] = NEG_INF;
        }
    } else {
#pragma unroll
        for (int h = 0; h < HEADS; h++) s[h] = -2e18f;
    }
#pragma unroll
    for (int h = 0; h < HEADS; h++) {
        float mx = s[h];
        for (int d = 16; d; d >>= 1) mx = fmaxf(mx, __shfl_xor_sync(0xffffffffu, mx, d));
        float e = expf(s[h] - mx);
        float ssum = e;
        for (int d = 16; d; d >>= 1) ssum += __shfl_xor_sync(0xffffffffu, ssum, d);
        if (lane < NNB) w[warp][h * NNB + lane] = e / ssum;
    }
    __syncwarp();

    // each lane owns 8 contiguous columns: one uint4 (8 fp16) per neighbor
    int c0 = lane * 8;              // 0..248
    int h = c0 >> 6;                // head (8-col group never crosses 64-col head)
    float acc[8];
#pragma unroll
    for (int q = 0; q < 8; q++) acc[q] = 0.f;
#pragma unroll
    for (int m = 0; m < NNB; m++) {
        float ww = w[warp][h * NNB + m];
        const uint4 v4 = *reinterpret_cast<const uint4*>(
            &g_V16[(size_t)js[warp][m] * 256 + c0]);
        const __half2* vh = reinterpret_cast<const __half2*>(&v4);
#pragma unroll
        for (int p = 0; p < 4; p++) {
            float2 vv = __half22float2(vh[p]);
            acc[2 * p]     += ww * vv.x;
            acc[2 * p + 1] += ww * vv.y;
        }
    }
    __half2 outv[4];
#pragma unroll
    for (int p = 0; p < 4; p++)
        outv[p] = __floats2half2_rn(acc[2 * p], acc[2 * p + 1]);
    *reinterpret_cast<uint4*>(&g_sh16[(size_t)n * H + c0]) =
        *reinterpret_cast<uint4*>(outv);
}

// ---------------- launch -------------------------------------------------------
static void* symaddr(const void* s) {
    void* p = nullptr;
    cudaGetSymbolAddress(&p, s);
    return p;
}

extern "C" void kernel_launch(void* const* d_in, const int* in_sizes, int n_in,
                              void* d_out, int out_size) {
    const float* fmess = (const float*)d_in[0];
    const int*   bgraph = (const int*)d_in[1];
    const float* Wq = (const float*)d_in[2];
    const float* bq = (const float*)d_in[3];
    const float* Wk = (const float*)d_in[4];
    const float* bk = (const float*)d_in[5];
    const float* Wv = (const float*)d_in[6];
    const float* bv = (const float*)d_in[7];
    const float* alpha = (const float*)d_in[8];
    const float* abias = (const float*)d_in[9];
    const float* Wz = (const float*)d_in[10];
    const float* bz = (const float*)d_in[11];
    const float* Wr = (const float*)d_in[12];
    const float* Ur = (const float*)d_in[13];
    const float* bur = (const float*)d_in[14];
    const float* Wh = (const float*)d_in[15];
    const float* bh = (const float*)d_in[16];
    float* out = (float*)d_out;

    const __half* a_h16  = (const __half*)symaddr(g_h16);
    const __half* a_sh16 = (const __half*)symaddr(g_sh16);
    const __half* a_rs16 = (const __half*)symaddr(g_rs16);
    const __half* a_f16  = (const __half*)symaddr(g_f16);
    const __half* w_kv   = (const __half*)symaddr(g_Wkv16);
    const __half* w_zr   = (const __half*)symaddr(g_Wzr16);
    const __half* w_h2   = (const __half*)symaddr(g_Wh216);
    const __half* w_pr   = (const __half*)symaddr(g_Wpre16);
    const float* b_kv  = (const float*)symaddr(g_bkv);
    const float* b_pre = (const float*)symaddr(g_bpre);

    cudaFuncSetAttribute(gemm_mma, cudaFuncAttributeMaxDynamicSharedMemorySize, SMEM_DYN);

    setup_all<<<PAD_BLOCKS + 64, 256>>>(fmess, Wq, bq, Wk, bk, Wv, bv,
                                        Wz, bz, Wr, Ur, bur, Wh, bh);

    // PRE: [F(768) | qscore] = fmess @ Wpre^T + bpre
    gemm_mma<<<dim3(8, 128), 256, SMEM_DYN>>>(a_f16, w_pr, b_pre, alpha,
                                              KQ, GT_PRE, nullptr);

    // ---- step 0 (exact rank-1 shortcut) ----
    zr0_kernel<<<N_MSG * H / 512, 256>>>(bv);
    gemm_mma<<<dim3(2, 128), 256, SMEM_DYN>>>(a_rs16, w_h2, nullptr, nullptr,
                                              H, GT_FINAL, nullptr);

    // ---- steps 1..DEPTH-1 ----
    for (int step = 1; step < DEPTH; step++) {
        gemm_mma<<<dim3(4, 128), 256, SMEM_DYN>>>(a_h16, w_kv, b_kv, alpha,
                                                  H, GT_KV, nullptr);
        attn_kernel<<<N_MSG / 8, 256>>>(bgraph, abias);
        gemm_mma<<<dim3(4, 128), 256, SMEM_DYN>>>(a_sh16, w_zr, nullptr, nullptr,
                                                  H, GT_ZR, nullptr);
        gemm_mma<<<dim3(2, 128), 256, SMEM_DYN>>>(a_rs16, w_h2, nullptr, nullptr,
                                                  H, GT_FINAL,
                                                  step == DEPTH - 1 ? out : nullptr);
    }
    (void)in_sizes; (void)n_in; (void)out_size;
}